// round 2
// baseline (speedup 1.0000x reference)
#include <cuda_runtime.h>

// Problem constants (fixed by the reference):
//   N=4096 samples, D=128 input dim, P=128 pe dim (== D), H=256 hidden.
#define NN 4096
#define DD 128
#define HH 256
#define JT 16   // j-tile per block in K2

// Scratch: base[n][h] = (x @ W1[:D])[n][h] + b1[h]
__device__ float g_base[NN * HH];

typedef unsigned long long u64;

__device__ __forceinline__ u64 pk2(float x, float y) {
    u64 r; asm("mov.b64 %0, {%1, %2};" : "=l"(r) : "f"(x), "f"(y)); return r;
}
__device__ __forceinline__ u64 fma2_(u64 a, u64 b, u64 c) {
    u64 d; asm("fma.rn.f32x2 %0, %1, %2, %3;" : "=l"(d) : "l"(a), "l"(b), "l"(c)); return d;
}
__device__ __forceinline__ u64 add2_(u64 a, u64 b) {
    u64 d; asm("add.rn.f32x2 %0, %1, %2;" : "=l"(d) : "l"(a), "l"(b)); return d;
}
__device__ __forceinline__ u64 relu2_(u64 a) {
    float x, y;
    asm("mov.b64 {%0, %1}, %2;" : "=f"(x), "=f"(y) : "l"(a));
    x = fmaxf(x, 0.0f); y = fmaxf(y, 0.0f);
    return pk2(x, y);
}
__device__ __forceinline__ float2 unpk(u64 a) {
    float2 v; asm("mov.b64 {%0, %1}, %2;" : "=f"(v.x), "=f"(v.y) : "l"(a)); return v;
}

// ---------------------------------------------------------------------------
// K1: base = x @ W1[:D] + b1   (4096 x 256, K=128)
// Tiles: 64(n) x 64(h) x 32(k); 256 threads; 4x4 register microtile.
// Also writes the leading ones column of the output (blockIdx.y == 0).
// ---------------------------------------------------------------------------
__global__ __launch_bounds__(256) void nimo_base_kernel(
    const float* __restrict__ x, const float* __restrict__ W1,
    const float* __restrict__ b1, float* __restrict__ out)
{
    __shared__ __align__(16) float xs[32][68];  // [k][n] transposed, padded
    __shared__ __align__(16) float ws[32][68];  // [k][h], padded

    const int tid = threadIdx.x;
    const int n0 = blockIdx.x * 64;
    const int h0 = blockIdx.y * 64;
    const int tx = tid & 15;   // h group (0..15) -> 4 h
    const int ty = tid >> 4;   // n group (0..15) -> 4 n

    float acc[4][4];
#pragma unroll
    for (int i = 0; i < 4; i++)
#pragma unroll
        for (int j = 0; j < 4; j++) acc[i][j] = 0.0f;

    for (int kt = 0; kt < DD; kt += 32) {
#pragma unroll
        for (int i = 0; i < 8; i++) {           // 64n x 32k = 2048 elems
            int e = tid + i * 256;
            int r = e >> 5, k = e & 31;
            xs[k][r] = x[(n0 + r) * DD + kt + k];
        }
#pragma unroll
        for (int i = 0; i < 8; i++) {           // 32k x 64h = 2048 elems
            int e = tid + i * 256;
            int k = e >> 6, c = e & 63;
            ws[k][c] = W1[(kt + k) * HH + h0 + c];
        }
        __syncthreads();
#pragma unroll
        for (int kk = 0; kk < 32; kk++) {
            float4 xv = *(const float4*)&xs[kk][ty * 4];
            float4 wv = *(const float4*)&ws[kk][tx * 4];
            acc[0][0] += xv.x * wv.x; acc[0][1] += xv.x * wv.y;
            acc[0][2] += xv.x * wv.z; acc[0][3] += xv.x * wv.w;
            acc[1][0] += xv.y * wv.x; acc[1][1] += xv.y * wv.y;
            acc[1][2] += xv.y * wv.z; acc[1][3] += xv.y * wv.w;
            acc[2][0] += xv.z * wv.x; acc[2][1] += xv.z * wv.y;
            acc[2][2] += xv.z * wv.z; acc[2][3] += xv.z * wv.w;
            acc[3][0] += xv.w * wv.x; acc[3][1] += xv.w * wv.y;
            acc[3][2] += xv.w * wv.z; acc[3][3] += xv.w * wv.w;
        }
        __syncthreads();
    }

    float4 bv = *(const float4*)&b1[h0 + tx * 4];
#pragma unroll
    for (int i = 0; i < 4; i++) {
        float4 o;
        o.x = acc[i][0] + bv.x; o.y = acc[i][1] + bv.y;
        o.z = acc[i][2] + bv.z; o.w = acc[i][3] + bv.w;
        *(float4*)&g_base[(n0 + ty * 4 + i) * HH + h0 + tx * 4] = o;
    }

    // ones column
    if (blockIdx.y == 0 && tid < 64) out[(n0 + tid) * (DD + 1)] = 1.0f;
}

// ---------------------------------------------------------------------------
// K2: per (n, j):
//   g = sum_h relu(base[n,h] + W1[D+j,h] - x[n,j]*W1[j,h]) * W2[h]
//   out[n, 1+j] = x[n,j] * (1 + b2 + g)
//
// Warp layout: lane = hg*4 + nl; hg in [0,8) owns h-segment [hg*32, hg*32+32);
// nl in [0,4) owns one n. base & W2 segments live in registers for the whole
// j-loop. W1/pe rows for the block's JT=16 j's are staged in shared memory
// with an XOR-chunk swizzle (segment stride 128B would otherwise be a perfect
// 8-way bank conflict). Reduction = 3 shfl_xor (4,8,16) covering 4 n at once.
// Grid: (128 n-tiles of 32) x (8 j-tiles of 16).
// ---------------------------------------------------------------------------
__global__ __launch_bounds__(256, 2) void nimo_main_kernel(
    const float* __restrict__ x, const float* __restrict__ W1,
    const float* __restrict__ W2, const float* __restrict__ b2,
    float* __restrict__ out)
{
    __shared__ __align__(16) float ws[2 * JT * HH];  // rows 0..15: W1[j0+r], 16..31: W1[128+j0+r]
    __shared__ float xs[JT][33];                     // x tile [j'][n']

    const int tid  = threadIdx.x;
    const int lane = tid & 31;
    const int warp = tid >> 5;
    const int nl   = lane & 3;   // n within quad
    const int hg   = lane >> 2;  // h-segment (32 h)
    const int n0   = blockIdx.x * 32;
    const int j0   = blockIdx.y * JT;
    const int n    = n0 + warp * 4 + nl;

    // ---- stage x tile: xs[j'][n'] ----
    {
        int jj = tid & (JT - 1), nn = tid >> 4;  // 256 threads cover 16j x 16n; two passes
        xs[jj][nn]      = x[(n0 + nn) * DD + j0 + jj];
        xs[jj][nn + 16] = x[(n0 + nn + 16) * DD + j0 + jj];
    }

    // ---- stage W1/pe rows (swizzled chunks) ----
#pragma unroll
    for (int pass = 0; pass < 8; pass++) {
        int g = tid + pass * 256;        // global chunk 0..2047 (16B chunks)
        int r = g >> 6;                  // row 0..31
        int q = g & 63;                  // logical chunk within row
        int src_row = (r < JT) ? (j0 + r) : (DD + j0 + (r - JT));
        float4 v = *(const float4*)&W1[src_row * HH + q * 4];
        int p = q ^ ((q >> 3) & 7);      // physical (swizzled) chunk
        *(float4*)&ws[r * HH + p * 4] = v;
    }

    // ---- persistent: base segment (this lane's n, h in [hg*32, hg*32+32)) + W2 segment ----
    u64 bp[16], wp[16];
    {
        const float* br = &g_base[n * HH + hg * 32];
        const float* wr = &W2[hg * 32];
#pragma unroll
        for (int c = 0; c < 8; c++) {
            float4 bv = *(const float4*)&br[c * 4];
            float4 wv = *(const float4*)&wr[c * 4];
            bp[2 * c]     = pk2(bv.x, bv.y);
            bp[2 * c + 1] = pk2(bv.z, bv.w);
            wp[2 * c]     = pk2(wv.x, wv.y);
            wp[2 * c + 1] = pk2(wv.z, wv.w);
        }
    }
    const float b2v = b2[0];

    __syncthreads();

#pragma unroll 1
    for (int jj = 0; jj < JT; jj++) {
        const float xj = xs[jj][warp * 4 + nl];
        const u64 nx2 = pk2(-xj, -xj);
        const float* w1r = &ws[jj * HH];
        const float* per = &ws[(JT + jj) * HH];
        u64 acc0 = 0ull, acc1 = 0ull;
#pragma unroll
        for (int c = 0; c < 8; c++) {
            int p = (hg * 8 + c) ^ hg;   // physical chunk for this lane's segment
            float4 w1v = *(const float4*)&w1r[p * 4];
            float4 pev = *(const float4*)&per[p * 4];
            u64 w1a = pk2(w1v.x, w1v.y), w1b = pk2(w1v.z, w1v.w);
            u64 pea = pk2(pev.x, pev.y), peb = pk2(pev.z, pev.w);
            u64 v0 = add2_(fma2_(nx2, w1a, pea), bp[2 * c]);
            u64 v1 = add2_(fma2_(nx2, w1b, peb), bp[2 * c + 1]);
            v0 = relu2_(v0);
            v1 = relu2_(v1);
            acc0 = fma2_(v0, wp[2 * c], acc0);
            acc1 = fma2_(v1, wp[2 * c + 1], acc1);
        }
        u64 accp = add2_(acc0, acc1);
        float2 a = unpk(accp);
        float s = a.x + a.y;
        s += __shfl_xor_sync(0xffffffffu, s, 4);
        s += __shfl_xor_sync(0xffffffffu, s, 8);
        s += __shfl_xor_sync(0xffffffffu, s, 16);
        if (hg == 0) out[n * (DD + 1) + 1 + j0 + jj] = xj * (1.0f + b2v + s);
    }
}

extern "C" void kernel_launch(void* const* d_in, const int* in_sizes, int n_in,
                              void* d_out, int out_size)
{
    const float* x  = (const float*)d_in[0];
    const float* W1 = (const float*)d_in[1];
    const float* b1 = (const float*)d_in[2];
    const float* W2 = (const float*)d_in[3];
    const float* b2 = (const float*)d_in[4];
    float* out = (float*)d_out;

    // K1: base GEMM + ones column. grid: 64 n-tiles x 4 h-tiles.
    nimo_base_kernel<<<dim3(64, 4), 256>>>(x, W1, b1, out);
    // K2: masked-MLP evaluation. grid: 128 n-tiles x 8 j-tiles.
    nimo_main_kernel<<<dim3(128, 8), 256>>>(x, W1, W2, b2, out);
}